// round 6
// baseline (speedup 1.0000x reference)
#include <cuda_runtime.h>
#include <cstdint>

// Persistent double-buffered FWHT, N=4096 fp32.
// Grid = 912 CTAs (6/SM * 152 SMs), each CTA grid-strides over rows.
// Per row: cp.async.cg prefetches the NEXT row (16KB) into the alternate
// smem buffer while the current row is computed from the other buffer.
//
// 12 butterfly stages, 3 register rounds (proven R5 bit mapping):
//   round 1: bits {0,1,7,8}   (vector LDS.128 from prefetch buffer)
//   round 2: bits {2,3,4,5}   (swizzled smem exchange, in-place)
//   round 3: bits {6,9,10,11} (swizzled read; coalesced scalar STG)
// XOR swizzle on float4 slots: s' = s ^ ((s>>4)&7) -> all patterns
// bank-conflict-free. Output scaled by 2^-6 (normalized Hadamard).

#define HN       4096
#define NTHREADS 256
#define RPT      16
#define NSLOTS   (HN / 4)     // 1024 float4 slots per row buffer

__device__ __forceinline__ void cp_async16(uint32_t saddr, const void* gptr) {
    asm volatile("cp.async.cg.shared.global [%0], [%1], 16;"
                 :: "r"(saddr), "l"(gptr) : "memory");
}
__device__ __forceinline__ void cp_commit() {
    asm volatile("cp.async.commit_group;" ::: "memory");
}
__device__ __forceinline__ void cp_wait0() {
    asm volatile("cp.async.wait_group 0;" ::: "memory");
}

__global__ __launch_bounds__(NTHREADS, 6)
void fwht_pipe_kernel(const float* __restrict__ X, float* __restrict__ Y,
                      int nrows)
{
    __shared__ float4 buf[2][NSLOTS];          // 2 x 16 KB

    const int t = threadIdx.x;
    const int w = t >> 5;          // warp 0..7
    const int l = t & 31;          // lane

    // thread-invariant index precompute
    const int slot0 = w * 128 + l;             // + j*32 for j=0..3
    const int p2    = l & 3;                   // round-2 float lane
    const int q2    = (l >> 2) & 1;
    const int u2r   = (l >> 3) & 3;
    const int sbase = 16 * q2 + 32 * u2r + 128 * w;
    const int sig   = q2 + 2 * u2r;
    const int u3    = w >> 1;                  // n7,n8 in round 3
    const int m3    = ((w & 1) << 5) | l;      // n0..5
    const int mq    = m3 >> 2;
    const int mp    = m3 & 3;
    const int obase = m3 + 128 * u3;

    const uint32_t sb0 = (uint32_t)__cvta_generic_to_shared(&buf[0][0]);
    const uint32_t sb1 = (uint32_t)__cvta_generic_to_shared(&buf[1][0]);

    const int G = gridDim.x;
    int row = blockIdx.x;
    if (row >= nrows) return;

    // ---- prologue: prefetch first row into buf[0] ----
    {
        const float4* xg = reinterpret_cast<const float4*>(X) + (size_t)row * NSLOTS;
        #pragma unroll
        for (int j = 0; j < 4; j++)
            cp_async16(sb0 + (uint32_t)(slot0 + j * 32) * 16u, xg + slot0 + j * 32);
        cp_commit();
    }

    int p = 0;
    for (; row < nrows; row += G, p ^= 1) {
        float* const sf = reinterpret_cast<float*>(buf[p]);
        float*       __restrict__ y = Y + (size_t)row * HN;

        cp_wait0();
        __syncthreads();                        // buf[p] ready for everyone

        // prefetch next row into buf[p^1] (its last reads finished before
        // the barrier above, at the end of the previous iteration)
        const int next = row + G;
        if (next < nrows) {
            const uint32_t sbn = p ? sb0 : sb1;
            const float4* xg = reinterpret_cast<const float4*>(X) + (size_t)next * NSLOTS;
            #pragma unroll
            for (int j = 0; j < 4; j++)
                cp_async16(sbn + (uint32_t)(slot0 + j * 32) * 16u, xg + slot0 + j * 32);
            cp_commit();
        }

        float v[RPT];

        // ---- Round 1: read slots w*128 + j*32 + l (LDS.128, conflict-free)
        #pragma unroll
        for (int j = 0; j < 4; j++) {
            float4 a = buf[p][slot0 + j * 32];
            v[4*j+0] = a.x; v[4*j+1] = a.y; v[4*j+2] = a.z; v[4*j+3] = a.w;
        }
        // reg r = j*4+k : bits r0,r1 = n0,n1 ; r2,r3 = n7,n8
        #pragma unroll
        for (int st = 1; st < RPT; st <<= 1) {
            #pragma unroll
            for (int i = 0; i < RPT; i++) {
                if (!(i & st)) {
                    float a = v[i], b = v[i ^ st];
                    v[i] = a + b;  v[i ^ st] = a - b;
                }
            }
        }

        __syncthreads();                        // all round-1 reads done

        // ---- Exchange 1: write swizzled float4 slots ----
        #pragma unroll
        for (int j = 0; j < 4; j++) {
            int s  = slot0 + j * 32;
            int ss = s ^ ((s >> 4) & 7);
            buf[p][ss] = make_float4(v[4*j+0], v[4*j+1], v[4*j+2], v[4*j+3]);
        }
        __syncthreads();

        // ---- Round 2: bits 2..5 ----
        #pragma unroll
        for (int i = 0; i < RPT; i++) {
            int ss = (sbase + i) ^ sig;
            v[i] = sf[ss * 4 + p2];
        }
        #pragma unroll
        for (int st = 1; st < RPT; st <<= 1) {
            #pragma unroll
            for (int i = 0; i < RPT; i++) {
                if (!(i & st)) {
                    float a = v[i], b = v[i ^ st];
                    v[i] = a + b;  v[i ^ st] = a - b;
                }
            }
        }
        // write back to the same thread-private addresses (no barrier needed)
        #pragma unroll
        for (int i = 0; i < RPT; i++) {
            int ss = (sbase + i) ^ sig;
            sf[ss * 4 + p2] = v[i];
        }
        __syncthreads();

        // ---- Round 3: bits {6,9,10,11} ----
        #pragma unroll
        for (int i2 = 0; i2 < RPT; i2++) {
            int b6 = i2 & 1, hi = i2 >> 1;
            int s  = mq + 16 * b6 + 32 * u3 + 128 * hi;
            int sg = b6 + 2 * u3;
            v[i2] = sf[(s ^ sg) * 4 + mp];
        }
        #pragma unroll
        for (int st = 1; st < RPT; st <<= 1) {
            #pragma unroll
            for (int i = 0; i < RPT; i++) {
                if (!(i & st)) {
                    float a = v[i], b = v[i ^ st];
                    v[i] = a + b;  v[i ^ st] = a - b;
                }
            }
        }

        // ---- Store: n = m3 + 64*b6 + 128*u3 + 512*hi (coalesced 128B) ----
        #pragma unroll
        for (int i2 = 0; i2 < RPT; i2++) {
            int b6 = i2 & 1, hi = i2 >> 1;
            __stcs(&y[obase + 64 * b6 + 512 * hi], v[i2] * 0.015625f); // *2^-6
        }
        // NOTE: next iteration's top __syncthreads (after cp_wait0) protects
        // buf[p^1] reuse; round-3 reads of buf[p] complete before it.
    }
}

extern "C" void kernel_launch(void* const* d_in, const int* in_sizes, int n_in,
                              void* d_out, int out_size)
{
    const float* X = (const float*)d_in[0];   // [8192, 4096] fp32
    // d_in[1]: dense Hadamard matrix H — unused (FWHT).
    float* Y = (float*)d_out;

    const int nrows = in_sizes[0] / HN;       // 8192
    int grid = 912;                           // 6 CTAs/SM * 152 SMs
    if (grid > nrows) grid = nrows;
    fwht_pipe_kernel<<<grid, NTHREADS>>>(X, Y, nrows);
}

// round 7
// speedup vs baseline: 1.5239x; 1.5239x over previous
#include <cuda_runtime.h>

// Fast Walsh-Hadamard Transform, N=4096 fp32, one row per 256-thread CTA.
// All 12 stages in registers across 3 rounds; bit ownership chosen so that
// EVERY global memory instruction is lane-contiguous (no strided LDG):
//   round 1: bits {0,1,7,8}   loads: LDG.128, warp reads 512B contiguous
//   round 2: bits {2,3,4,5}   via swizzled smem exchange
//   round 3: bits {6,9,10,11} via swizzled smem exchange; scalar coalesced STG
// Smem uses XOR swizzle on float4 slots:  s' = s ^ ((s>>4)&7)  -> all four
// access patterns (vec write, scalar read, scalar write, scalar read) are
// bank-conflict-free.  Output scaled by 2^-6 (normalized Hadamard).
//
// R7: __launch_bounds__(256, 8) to force <=32 regs (8 CTAs/SM, 100% occ),
//     __ldcs/__stcs streaming hints on the read-once/write-once global data.

#define HN       4096
#define NTHREADS 256
#define RPT      16

__global__ __launch_bounds__(NTHREADS, 8)
void fwht_kernel(const float* __restrict__ X, float* __restrict__ Y)
{
    __shared__ float4 s4[HN / 4];              // 16 KB, no padding needed
    float* const sf = reinterpret_cast<float*>(s4);

    const size_t row = blockIdx.x;
    const float* __restrict__ x = X + row * HN;
    float*       __restrict__ y = Y + row * HN;

    const int t = threadIdx.x;
    const int w = t >> 5;          // warp 0..7
    const int l = t & 31;          // lane

    float v[RPT];

    // ---- Round 1 load: instr j reads float4 slot  w*128 + j*32 + l ----
    // (warp-contiguous 512B per instruction -> 4 L1 wavefronts each)
    {
        const float4* __restrict__ xv = reinterpret_cast<const float4*>(x);
        #pragma unroll
        for (int j = 0; j < 4; j++) {
            float4 a = __ldcs(xv + w * 128 + j * 32 + l);
            v[4*j+0] = a.x; v[4*j+1] = a.y; v[4*j+2] = a.z; v[4*j+3] = a.w;
        }
    }
    // reg index r = j*4 + k  maps to n-bits: r0,r1 = n0,n1 ; r2,r3 = n7,n8
    #pragma unroll
    for (int st = 1; st < RPT; st <<= 1) {
        #pragma unroll
        for (int i = 0; i < RPT; i++) {
            if (!(i & st)) {
                float a = v[i], b = v[i ^ st];
                v[i]      = a + b;
                v[i ^ st] = a - b;
            }
        }
    }

    // ---- Exchange 1 write: float4 slot s = w*128 + j*32 + l, swizzled ----
    #pragma unroll
    for (int j = 0; j < 4; j++) {
        int s  = w * 128 + j * 32 + l;
        int ss = s ^ ((s >> 4) & 7);
        s4[ss] = make_float4(v[4*j+0], v[4*j+1], v[4*j+2], v[4*j+3]);
    }
    __syncthreads();

    // ---- Round 2: thread fixes p=n0n1, q=n6, u=n7n8, w=n9..11; i = n2..5 ----
    const int p  = l & 3;
    const int q  = (l >> 2) & 1;
    const int u  = (l >> 3) & 3;
    const int sbase = 16 * q + 32 * u + 128 * w;   // slot base (i adds 0..15)
    const int sig   = q + 2 * u;                   // = ((s>>4)&7) for these slots
    #pragma unroll
    for (int i = 0; i < RPT; i++) {
        int ss = (sbase + i) ^ sig;
        v[i] = sf[ss * 4 + p];
    }
    // reg index i = n-bits 2..5
    #pragma unroll
    for (int st = 1; st < RPT; st <<= 1) {
        #pragma unroll
        for (int i = 0; i < RPT; i++) {
            if (!(i & st)) {
                float a = v[i], b = v[i ^ st];
                v[i]      = a + b;
                v[i ^ st] = a - b;
            }
        }
    }
    // write back to the same (thread-private) addresses — no barrier needed first
    #pragma unroll
    for (int i = 0; i < RPT; i++) {
        int ss = (sbase + i) ^ sig;
        sf[ss * 4 + p] = v[i];
    }
    __syncthreads();

    // ---- Round 3: thread fixes m = n0..5, u2 = n7n8 ; i2 -> {n6, n9..11} ----
    const int u2 = w >> 1;                 // n7,n8
    const int m  = ((w & 1) << 5) | l;     // n0..5
    const int mq = m >> 2;                 // slot low bits
    const int mp = m & 3;
    #pragma unroll
    for (int i2 = 0; i2 < RPT; i2++) {
        int b6 = i2 & 1, hi = i2 >> 1;
        int s  = mq + 16 * b6 + 32 * u2 + 128 * hi;
        int sg = b6 + 2 * u2;              // = ((s>>4)&7)
        v[i2] = sf[(s ^ sg) * 4 + mp];
    }
    // reg index i2: bit0 = n6, bits1..3 = n9..11
    #pragma unroll
    for (int st = 1; st < RPT; st <<= 1) {
        #pragma unroll
        for (int i = 0; i < RPT; i++) {
            if (!(i & st)) {
                float a = v[i], b = v[i ^ st];
                v[i]      = a + b;
                v[i ^ st] = a - b;
            }
        }
    }

    // ---- Store: n = m + 64*b6 + 128*u2 + 512*hi ; lanes contiguous 128B ----
    const int obase = m + 128 * u2;
    #pragma unroll
    for (int i2 = 0; i2 < RPT; i2++) {
        int b6 = i2 & 1, hi = i2 >> 1;
        __stcs(&y[obase + 64 * b6 + 512 * hi], v[i2] * 0.015625f);   // * 2^-6
    }
}

extern "C" void kernel_launch(void* const* d_in, const int* in_sizes, int n_in,
                              void* d_out, int out_size)
{
    const float* X = (const float*)d_in[0];   // [8192, 4096] fp32
    // d_in[1]: dense Hadamard matrix H — unused (FWHT).
    float* Y = (float*)d_out;

    const int rows = in_sizes[0] / HN;        // 8192
    fwht_kernel<<<rows, NTHREADS>>>(X, Y);
}